// round 1
// baseline (speedup 1.0000x reference)
#include <cuda_runtime.h>
#include <cuda_bf16.h>
#include <math.h>

// Problem constants
#define BATCH   256
#define NEI     128
#define NRELS   5000
#define NSUP    32
#define DIM     128
#define TOPK    64

// d_out (float32) segment offsets (flatten+concat of the 5 reference outputs)
#define OFF_TN  0           // tree_node      [256,3,64]
#define OFF_TE  49152       // tree_emb_all   [256,3,64,128]
#define OFF_PI  6340608     // parent_index   [256,3,64]
#define OFF_PN  6389760     // parent_node    [256,3,64]
#define OFF_AR  6438912     // aim_rel_all    [256,3,64]

typedef unsigned long long ull;

// ---------------- device scratch (static: no allocation allowed) -------------
__device__ float g_best[NRELS];               // max-over-support score per relation
__device__ float g_relgi[NRELS * 384];        // rel_emb @ W_ih^T + b_ih
__device__ float g_wT[2][128 * 384];          // [0]=W_ih^T, [1]=W_hh^T  (k-major)
__device__ int   g_e[3][BATCH * TOPK];
__device__ int   g_r[3][BATCH * TOPK];
__device__ int   g_p[3][BATCH * TOPK];

__device__ __forceinline__ ull umax64(ull a, ull b) { return a > b ? a : b; }

// ---------------- prep: transpose weights ------------------------------------
__global__ void prep_kernel(const float* __restrict__ wih, const float* __restrict__ whh) {
    int idx = blockIdx.x * blockDim.x + threadIdx.x;
    if (idx < 384 * 128) {
        int j = idx / 128, k = idx % 128;
        g_wT[0][k * 384 + j] = wih[idx];
        g_wT[1][k * 384 + j] = whh[idx];
    }
}

// ---------------- best[r] = max_s cos[support[s], r] --------------------------
__global__ void best_kernel(const float* __restrict__ cosm, const int* __restrict__ sup) {
    __shared__ int ss[NSUP];
    if (threadIdx.x < NSUP) ss[threadIdx.x] = sup[threadIdx.x];
    __syncthreads();
    int r = blockIdx.x * blockDim.x + threadIdx.x;
    if (r < NRELS) {
        float m = -3.4e38f;
        #pragma unroll
        for (int s = 0; s < NSUP; ++s)
            m = fmaxf(m, cosm[(long long)ss[s] * NRELS + r]);
        g_best[r] = m;
    }
}

// ---------------- rel_gi = rel_emb @ W_ih^T + b_ih ----------------------------
// 384 threads, 16 relations per block. Register-blocked matvec.
__global__ void __launch_bounds__(384) relgi_kernel(const float* __restrict__ rel_emb,
                                                    const float* __restrict__ b_ih) {
    const int rb = blockIdx.x * 16;
    const int tid = threadIdx.x;
    __shared__ float4 x4[16][32];
    float* xf = (float*)x4;
    for (int idx = tid; idx < 16 * 128; idx += 384) {
        int n = idx >> 7, d = idx & 127;
        int r = rb + n;
        xf[n * 128 + d] = (r < NRELS) ? rel_emb[r * 128 + d] : 0.f;
    }
    __syncthreads();
    const int j = tid;
    float acc[16];
    const float bj = b_ih[j];
    #pragma unroll
    for (int n = 0; n < 16; ++n) acc[n] = bj;
    const float* wt = g_wT[0];
    for (int k4 = 0; k4 < 32; ++k4) {
        float4 hv[16];
        #pragma unroll
        for (int n = 0; n < 16; ++n) hv[n] = x4[n][k4];
        #pragma unroll
        for (int kk = 0; kk < 4; ++kk) {
            float w = wt[(k4 * 4 + kk) * 384 + j];
            #pragma unroll
            for (int n = 0; n < 16; ++n) {
                float hc = (kk == 0) ? hv[n].x : (kk == 1) ? hv[n].y : (kk == 2) ? hv[n].z : hv[n].w;
                acc[n] = fmaf(w, hc, acc[n]);
            }
        }
    }
    #pragma unroll
    for (int n = 0; n < 16; ++n) {
        int r = rb + n;
        if (r < NRELS) g_relgi[r * 384 + j] = acc[n];
    }
}

// ---------------- expand: score + stable top-64 -------------------------------
// One block per batch row. 64-bit key = (ordered(score)<<32) | (NCAND-1-i):
// u64 max == (score desc, index asc) == XLA TopK stable tie-break.
template <int NCAND, int NT>
__global__ void expand_kernel(const int2* __restrict__ edge,
                              const int* __restrict__ query_head,
                              float* __restrict__ out, int step) {
    extern __shared__ unsigned char sraw[];
    ull* keys  = (ull*)sraw;
    ull* lmax  = keys + NCAND;
    ull* wmax  = lmax + NT;
    int* s_top = (int*)(wmax + 32);
    int* s_cur = s_top + TOPK;
    __shared__ ull s_win;

    const int b = blockIdx.x;
    const int tid = threadIdx.x;
    constexpr int CHUNK = (NCAND + NT - 1) / NT;

    if (step == 0) {
        if (tid == 0) s_cur[0] = query_head[b];
    } else {
        if (tid < TOPK) s_cur[tid] = g_e[step - 1][b * TOPK + tid];
    }
    __syncthreads();

    // Phase A: score all candidates, build keys, cache per-thread stripe max.
    ull mymax = 0;
    #pragma unroll
    for (int m = 0; m < CHUNK; ++m) {
        int i = tid + m * NT;
        if (i < NCAND) {
            int c = i >> 7, n = i & 127;
            int ent = s_cur[c];
            int2 pr = __ldg(&edge[(long long)ent * NEI + n]);
            float s = g_best[pr.y];
            unsigned u = __float_as_uint(s);
            u = (u & 0x80000000u) ? ~u : (u | 0x80000000u);
            ull key = ((ull)u << 32) | (unsigned)(NCAND - 1 - i);
            keys[i] = key;
            mymax = umax64(mymax, key);
        }
    }
    lmax[tid] = mymax;
    __syncthreads();

    // Phase B: 64 iterations of block argmax with cached local maxima.
    const int lane = tid & 31, wid = tid >> 5;
    constexpr int NW = NT / 32;
    for (int it = 0; it < TOPK; ++it) {
        ull v = lmax[tid];
        #pragma unroll
        for (int off = 16; off > 0; off >>= 1)
            v = umax64(v, __shfl_down_sync(0xffffffffu, v, off));
        if (lane == 0) wmax[wid] = v;
        __syncthreads();
        if (wid == 0) {
            v = (lane < NW) ? wmax[lane] : 0ull;
            #pragma unroll
            for (int off = 16; off > 0; off >>= 1)
                v = umax64(v, __shfl_down_sync(0xffffffffu, v, off));
            if (lane == 0) s_win = v;
        }
        __syncthreads();
        ull w = s_win;
        int i = NCAND - 1 - (int)(unsigned)(w & 0xffffffffu);
        if (tid == (i & (NT - 1))) {
            keys[i] = 0ull;
            ull mm = 0;
            #pragma unroll
            for (int m = 0; m < CHUNK; ++m) {
                int ii = tid + m * NT;
                if (ii < NCAND) mm = umax64(mm, keys[ii]);
            }
            lmax[tid] = mm;
            s_top[it] = i;
        }
        __syncthreads();
    }

    // Phase C: emit results for the 64 winners (in selection order).
    if (tid < TOPK) {
        int i = s_top[tid];
        int c = i >> 7, n = i & 127;
        int ent = s_cur[c];
        int2 pr = __ldg(&edge[(long long)ent * NEI + n]);
        int j = tid;
        int gidx = b * TOPK + j;
        g_e[step][gidx] = pr.x;
        g_r[step][gidx] = pr.y;
        g_p[step][gidx] = c;
        out[OFF_TN + b * 192 + step * 64 + j] = (float)pr.x;
        if (step == 0) {
            out[OFF_PN + b * 192 + 0 * 64 + j] = (float)s_cur[0];
            out[OFF_PI + b * 192 + 2 * 64 + j] = (float)j;
        } else if (step == 1) {
            out[OFF_PI + b * 192 + 0 * 64 + j] = (float)c;
            out[OFF_PN + b * 192 + 1 * 64 + j] = (float)g_e[0][b * TOPK + c];
            out[OFF_AR + b * 192 + 0 * 64 + j] = (float)g_r[0][b * TOPK + c];
        } else {
            out[OFF_PI + b * 192 + 1 * 64 + j] = (float)c;
            out[OFF_PN + b * 192 + 2 * 64 + j] = (float)g_e[1][b * TOPK + c];
            out[OFF_AR + b * 192 + 1 * 64 + j] = (float)g_r[1][b * TOPK + c];
            out[OFF_AR + b * 192 + 2 * 64 + j] = (float)pr.y;
        }
    }
}

// ---------------- GRU step 1 (h = 0 => gh = b_hh, pure elementwise) ----------
__global__ void gru1_kernel(const float* __restrict__ b_hh, float* __restrict__ out) {
    const int b = blockIdx.x;
    for (int idx = threadIdx.x; idx < TOPK * 128; idx += blockDim.x) {
        int k = idx >> 7, d = idx & 127;
        int r = g_r[0][b * TOPK + k];
        const float* gi = &g_relgi[r * 384];
        float hr = b_hh[d], hz = b_hh[128 + d], hn = b_hh[256 + d];
        float rg = 1.f / (1.f + expf(-(gi[d] + hr)));
        float z  = 1.f / (1.f + expf(-(gi[128 + d] + hz)));
        float nn = tanhf(gi[256 + d] + rg * hn);
        out[OFF_TE + ((b * 3 + 0) * 64 + k) * 128 + d] = (1.f - z) * nn;
    }
}

// ---------------- GRU steps 2/3: gh = h_parent @ W_hh^T + b_hh ---------------
// grid (4, 256), 384 threads. 16 nodes per block, register-blocked matvec.
__global__ void __launch_bounds__(384) gru23_kernel(const float* __restrict__ b_hh,
                                                    float* __restrict__ out, int step) {
    const int b = blockIdx.y;
    const int kb = blockIdx.x * 16;
    const int tid = threadIdx.x;
    __shared__ float4 h4[16][32];
    __shared__ float gh[16][384];
    __shared__ int s_p[16], s_rel[16];
    if (tid < 16) {
        s_p[tid]   = g_p[step][b * TOPK + kb + tid];
        s_rel[tid] = g_r[step][b * TOPK + kb + tid];
    }
    __syncthreads();
    float* hflat = (float*)h4;
    for (int idx = tid; idx < 16 * 128; idx += 384) {
        int n = idx >> 7, d = idx & 127;
        int p = s_p[n];
        hflat[n * 128 + d] = out[OFF_TE + ((b * 3 + (step - 1)) * 64 + p) * 128 + d];
    }
    __syncthreads();

    const int j = tid;  // 0..383 : output row of gh
    float acc[16];
    const float bj = b_hh[j];
    #pragma unroll
    for (int n = 0; n < 16; ++n) acc[n] = bj;
    const float* wt = g_wT[1];
    for (int k4 = 0; k4 < 32; ++k4) {
        float4 hv[16];
        #pragma unroll
        for (int n = 0; n < 16; ++n) hv[n] = h4[n][k4];
        #pragma unroll
        for (int kk = 0; kk < 4; ++kk) {
            float w = wt[(k4 * 4 + kk) * 384 + j];
            #pragma unroll
            for (int n = 0; n < 16; ++n) {
                float hc = (kk == 0) ? hv[n].x : (kk == 1) ? hv[n].y : (kk == 2) ? hv[n].z : hv[n].w;
                acc[n] = fmaf(w, hc, acc[n]);
            }
        }
    }
    #pragma unroll
    for (int n = 0; n < 16; ++n) gh[n][j] = acc[n];
    __syncthreads();

    for (int idx = tid; idx < 16 * 128; idx += 384) {
        int n = idx >> 7, d = idx & 127;
        int r = s_rel[n];
        const float* gi = &g_relgi[r * 384];
        float ir = gi[d], iz = gi[128 + d], inn = gi[256 + d];
        float hr = gh[n][d], hz = gh[n][128 + d], hn = gh[n][256 + d];
        float hprev = hflat[n * 128 + d];
        float rg = 1.f / (1.f + expf(-(ir + hr)));
        float z  = 1.f / (1.f + expf(-(iz + hz)));
        float nn = tanhf(inn + rg * hn);
        out[OFF_TE + ((b * 3 + step) * 64 + kb + n) * 128 + d] = (1.f - z) * nn + z * hprev;
    }
}

// ---------------- launch ------------------------------------------------------
extern "C" void kernel_launch(void* const* d_in, const int* in_sizes, int n_in,
                              void* d_out, int out_size) {
    (void)in_sizes; (void)n_in; (void)out_size;
    const int*   qh      = (const int*)d_in[0];
    const int2*  edge    = (const int2*)d_in[1];
    const int*   sup     = (const int*)d_in[2];
    const float* cosm    = (const float*)d_in[3];
    const float* rel_emb = (const float*)d_in[4];
    const float* wih     = (const float*)d_in[5];
    const float* whh     = (const float*)d_in[6];
    const float* bih     = (const float*)d_in[7];
    const float* bhh     = (const float*)d_in[8];
    float* out = (float*)d_out;

    const size_t sm_small = 128ull * 8 + 128 * 8 + 32 * 8 + TOPK * 4 + TOPK * 4;
    const size_t sm_big   = 8192ull * 8 + 256 * 8 + 32 * 8 + TOPK * 4 + TOPK * 4;
    cudaFuncSetAttribute(expand_kernel<8192, 256>,
                         cudaFuncAttributeMaxDynamicSharedMemorySize, (int)sm_big);

    prep_kernel<<<192, 256>>>(wih, whh);
    best_kernel<<<(NRELS + 255) / 256, 256>>>(cosm, sup);
    relgi_kernel<<<(NRELS + 15) / 16, 384>>>(rel_emb, bih);

    expand_kernel<128, 128><<<BATCH, 128, sm_small>>>(edge, qh, out, 0);
    gru1_kernel<<<BATCH, 256>>>(bhh, out);

    expand_kernel<8192, 256><<<BATCH, 256, sm_big>>>(edge, qh, out, 1);
    gru23_kernel<<<dim3(4, BATCH), 384>>>(bhh, out, 1);

    expand_kernel<8192, 256><<<BATCH, 256, sm_big>>>(edge, qh, out, 2);
    gru23_kernel<<<dim3(4, BATCH), 384>>>(bhh, out, 2);
}